// round 2
// baseline (speedup 1.0000x reference)
#include <cuda_runtime.h>
#include <cstdint>
#include <math.h>

// ---------------- problem constants ----------------
namespace cfg {
constexpr int Bb    = 2;
constexpr int Ss    = 4096;
constexpr int DM    = 3584;
constexpr int Hh    = 112;
constexpr int DH    = 64;
constexpr int CHUNK = 256;
constexpr int INNER = Hh * DH;          // 7168
constexpr int M1    = Bb * Ss;          // 8192 rows (tokens)
constexpr int N1    = 2 * INNER;        // 14336 (x|z)
constexpr int K1    = DM;               // 3584
constexpr int N2    = DM;               // 3584
constexpr int K2    = INNER;            // 7168
constexpr int NCH   = Ss / CHUNK;       // 16 chunks
}

// ---------------- scratch (no cudaMalloc allowed) ----------------
__device__ float g_xz[(size_t)cfg::M1 * cfg::N1];   // ~470 MB
__device__ float g_y [(size_t)cfg::M1 * cfg::K2];   // ~235 MB

// ---------------- tf32 helpers ----------------
__device__ __forceinline__ uint32_t f2tf32(float x) {
    uint32_t u;
    asm("cvt.rna.tf32.f32 %0, %1;" : "=r"(u) : "f"(x));
    return u;
}

__device__ __forceinline__ void mma_m16n8k8(float d[4], const uint32_t a[4], const uint32_t b[2]) {
    asm volatile(
        "mma.sync.aligned.m16n8k8.row.col.f32.tf32.tf32.f32 "
        "{%0,%1,%2,%3}, {%4,%5,%6,%7}, {%8,%9}, {%0,%1,%2,%3};"
        : "+f"(d[0]), "+f"(d[1]), "+f"(d[2]), "+f"(d[3])
        : "r"(a[0]), "r"(a[1]), "r"(a[2]), "r"(a[3]),
          "r"(b[0]), "r"(b[1]));
}

// ---------------- GEMM: C[M,N] = A[M,K] * B[N,K]^T  (all row-major fp32, tf32 mma) ----------------
// BM=128, BN=128, BK=16, 256 threads, 8 warps as 2x4 (warp tile 64x32)
#define BM 128
#define BN 128
#define BKT 16
#define SST 20  // padded smem k-stride (conflict-free fragment loads)

__global__ __launch_bounds__(256)
void gemm_tf32_nt(const float* __restrict__ A, const float* __restrict__ Bm,
                  float* __restrict__ C, int M, int N, int K)
{
    __shared__ uint32_t As[2][BM * SST];
    __shared__ uint32_t Bs[2][BN * SST];

    // ---- L2-friendly tile swizzle (grouped rows) ----
    const int nTn = N / BN, nTm = M / BM;
    const int pid = blockIdx.x;
    constexpr int GROUP = 8;
    const int npg     = GROUP * nTn;
    const int gidx    = pid / npg;
    const int first_m = gidx * GROUP;
    const int gsz     = min(nTm - first_m, GROUP);
    const int inG     = pid % npg;
    const int tm      = first_m + (inG % gsz);
    const int tn      = inG / gsz;

    const int tid  = threadIdx.x;
    const int lane = tid & 31;
    const int wid  = tid >> 5;
    const int gq   = lane >> 2;     // group id (0..7)
    const int tg   = lane & 3;      // thread-in-group (0..3)
    const int m_w  = (wid >> 2) * 64;  // warp row base within tile
    const int n_w  = (wid & 3) * 32;   // warp col base within tile

    // ---- global load mapping: each thread loads 2 float4 per operand per k-tile ----
    const int lrow = tid >> 2;          // 0..63
    const int lk   = (tid & 3) << 2;    // 0,4,8,12
    const float* Ag = A  + (size_t)(tm * BM + lrow) * K + lk;
    const float* Bg = Bm + (size_t)(tn * BN + lrow) * K + lk;
    const size_t rstep = (size_t)64 * K;

    float4 pa0, pa1, pb0, pb1;
    pa0 = *(const float4*)(Ag);
    pa1 = *(const float4*)(Ag + rstep);
    pb0 = *(const float4*)(Bg);
    pb1 = *(const float4*)(Bg + rstep);

    auto stash = [&](int buf) {
        uint4 u;
        u.x = f2tf32(pa0.x); u.y = f2tf32(pa0.y); u.z = f2tf32(pa0.z); u.w = f2tf32(pa0.w);
        *(uint4*)&As[buf][lrow * SST + lk] = u;
        u.x = f2tf32(pa1.x); u.y = f2tf32(pa1.y); u.z = f2tf32(pa1.z); u.w = f2tf32(pa1.w);
        *(uint4*)&As[buf][(lrow + 64) * SST + lk] = u;
        u.x = f2tf32(pb0.x); u.y = f2tf32(pb0.y); u.z = f2tf32(pb0.z); u.w = f2tf32(pb0.w);
        *(uint4*)&Bs[buf][lrow * SST + lk] = u;
        u.x = f2tf32(pb1.x); u.y = f2tf32(pb1.y); u.z = f2tf32(pb1.z); u.w = f2tf32(pb1.w);
        *(uint4*)&Bs[buf][(lrow + 64) * SST + lk] = u;
    };

    stash(0);
    __syncthreads();

    float acc[4][4][4];
    #pragma unroll
    for (int i = 0; i < 4; i++)
        #pragma unroll
        for (int j = 0; j < 4; j++)
            #pragma unroll
            for (int r = 0; r < 4; r++) acc[i][j][r] = 0.f;

    const int nk = K / BKT;
    for (int kt = 0; kt < nk; ++kt) {
        const int cur = kt & 1;
        if (kt + 1 < nk) {
            const float* A2 = Ag + (size_t)(kt + 1) * BKT;
            const float* B2 = Bg + (size_t)(kt + 1) * BKT;
            pa0 = *(const float4*)(A2);
            pa1 = *(const float4*)(A2 + rstep);
            pb0 = *(const float4*)(B2);
            pb1 = *(const float4*)(B2 + rstep);
        }

        #pragma unroll
        for (int k8 = 0; k8 < 2; ++k8) {
            uint32_t af[4][4];
            uint32_t bf[4][2];
            #pragma unroll
            for (int mt = 0; mt < 4; mt++) {
                const int m0 = m_w + mt * 16 + gq;
                const uint32_t* p = &As[cur][m0 * SST + k8 * 8 + tg];
                af[mt][0] = p[0];
                af[mt][1] = p[8 * SST];
                af[mt][2] = p[4];
                af[mt][3] = p[8 * SST + 4];
            }
            #pragma unroll
            for (int nt = 0; nt < 4; nt++) {
                const int n0 = n_w + nt * 8 + gq;
                const uint32_t* p = &Bs[cur][n0 * SST + k8 * 8 + tg];
                bf[nt][0] = p[0];
                bf[nt][1] = p[4];
            }
            #pragma unroll
            for (int mt = 0; mt < 4; mt++)
                #pragma unroll
                for (int nt = 0; nt < 4; nt++)
                    mma_m16n8k8(acc[mt][nt], af[mt], bf[nt]);
        }

        if (kt + 1 < nk) stash(cur ^ 1);
        __syncthreads();
    }

    // ---- epilogue: c0,c1 at (row gq, cols 2tg,2tg+1); c2,c3 at row gq+8 ----
    #pragma unroll
    for (int mt = 0; mt < 4; mt++) {
        const int r0 = tm * BM + m_w + mt * 16 + gq;
        #pragma unroll
        for (int nt = 0; nt < 4; nt++) {
            const int c0 = tn * BN + n_w + nt * 8 + tg * 2;
            float2* p0 = (float2*)&C[(size_t)r0 * N + c0];
            float2* p1 = (float2*)&C[(size_t)(r0 + 8) * N + c0];
            *p0 = make_float2(acc[mt][nt][0], acc[mt][nt][1]);
            *p1 = make_float2(acc[mt][nt][2], acc[mt][nt][3]);
        }
    }
}

// ---------------- scan + sigmoid gate ----------------
// For each (b, t, h, d): h_c = h_{c-1}*A[h] + 0.1*x[b, c*CHUNK+t, h, d]; y = h_c * sigmoid(z)
__global__ __launch_bounds__(256)
void scan_gate_kernel(const float* __restrict__ A_log,
                      const float* __restrict__ xz,
                      float* __restrict__ y)
{
    using namespace cfg;
    const int idx   = blockIdx.x * blockDim.x + threadIdx.x;  // over Bb*CHUNK*INNER
    const int inner = idx % INNER;
    const int bt    = idx / INNER;
    const int t     = bt % CHUNK;
    const int b     = bt / CHUNK;

    const float Ah = expf(-fabsf(A_log[inner >> 6]));  // head = inner/64
    float hstate = 0.f;

    size_t xrow = ((size_t)b * Ss + t) * (size_t)N1 + inner;
    size_t yrow = ((size_t)b * Ss + t) * (size_t)INNER + inner;
    const size_t xstep = (size_t)CHUNK * N1;
    const size_t ystep = (size_t)CHUNK * INNER;

    #pragma unroll
    for (int c = 0; c < NCH; c++) {
        const float xv = xz[xrow];
        const float zv = xz[xrow + INNER];
        hstate = hstate * Ah + 0.1f * xv;
        const float sig = 1.f / (1.f + expf(-zv));
        y[yrow] = hstate * sig;
        xrow += xstep;
        yrow += ystep;
    }
}

// ---------------- launch ----------------
extern "C" void kernel_launch(void* const* d_in, const int* in_sizes, int n_in,
                              void* d_out, int out_size)
{
    using namespace cfg;
    const float* hs    = (const float*)d_in[0];  // [B,S,DM]
    const float* W_in  = (const float*)d_in[1];  // [2*INNER, DM]
    const float* W_out = (const float*)d_in[2];  // [DM, INNER]
    const float* A_log = (const float*)d_in[3];  // [H]
    float* out = (float*)d_out;                  // [B,S,DM]

    float *xz, *y;
    cudaGetSymbolAddress((void**)&xz, g_xz);
    cudaGetSymbolAddress((void**)&y,  g_y);

    // GEMM1: xz = hs @ W_in^T   (M=8192, N=14336, K=3584)
    gemm_tf32_nt<<<(M1 / BM) * (N1 / BN), 256>>>(hs, W_in, xz, M1, N1, K1);

    // scan + gate: y from xz
    const int total = Bb * CHUNK * INNER;     // 3,670,016
    scan_gate_kernel<<<total / 256, 256>>>(A_log, xz, y);

    // GEMM2: out = y @ W_out^T  (M=8192, N=3584, K=7168)
    gemm_tf32_nt<<<(M1 / BM) * (N2 / BN), 256>>>(y, W_out, out, M1, N2, K2);
}

// round 4
// speedup vs baseline: 1.2953x; 1.2953x over previous
#include <cuda_runtime.h>
#include <cstdint>
#include <math.h>

// ---------------- problem constants ----------------
namespace cfg {
constexpr int Bb    = 2;
constexpr int Ss    = 4096;
constexpr int DM    = 3584;
constexpr int Hh    = 112;
constexpr int DH    = 64;
constexpr int CHUNK = 256;
constexpr int INNER = Hh * DH;          // 7168
constexpr int M1    = Bb * Ss;          // 8192
constexpr int N1    = 2 * INNER;        // 14336
constexpr int K1    = DM;               // 3584
constexpr int N2    = DM;               // 3584
constexpr int K2    = INNER;            // 7168
constexpr int NCH   = Ss / CHUNK;       // 16
}

// ---------------- scratch (no cudaMalloc allowed) ----------------
__device__ float g_xz[(size_t)cfg::M1 * cfg::N1];   // GEMM1 out (natural order)
__device__ float g_y [(size_t)cfg::M1 * cfg::K2];   // scan out  (k-permuted, tf32-rounded)
__device__ float g_a1[(size_t)cfg::M1 * cfg::K1];   // hs    (k-permuted, tf32-rounded)
__device__ float g_w1[(size_t)cfg::N1 * cfg::K1];   // W_in  (k-permuted, tf32-rounded)
__device__ float g_w2[(size_t)cfg::N2 * cfg::K2];   // W_out (k-permuted, tf32-rounded)

// ---------------- helpers ----------------
__device__ __forceinline__ uint32_t f2tf32(float x) {
    uint32_t u;
    asm("cvt.rna.tf32.f32 %0, %1;" : "=r"(u) : "f"(x));
    return u;
}
__device__ __forceinline__ float rtf32(float x) { return __uint_as_float(f2tf32(x)); }

__device__ __forceinline__ uint32_t smem_u32(const void* p) {
    uint32_t a;
    asm("{ .reg .u64 t; cvta.to.shared.u64 t, %1; cvt.u32.u64 %0, t; }" : "=r"(a) : "l"(p));
    return a;
}
__device__ __forceinline__ void cp_async16(uint32_t smem_addr, const void* gmem) {
    asm volatile("cp.async.cg.shared.global [%0], [%1], 16;" :: "r"(smem_addr), "l"(gmem) : "memory");
}
__device__ __forceinline__ void mma_m16n8k8(float d[4], const uint32_t a[4], const uint32_t b[2]) {
    asm volatile(
        "mma.sync.aligned.m16n8k8.row.col.f32.tf32.tf32.f32 "
        "{%0,%1,%2,%3}, {%4,%5,%6,%7}, {%8,%9}, {%0,%1,%2,%3};"
        : "+f"(d[0]), "+f"(d[1]), "+f"(d[2]), "+f"(d[3])
        : "r"(a[0]), "r"(a[1]), "r"(a[2]), "r"(a[3]),
          "r"(b[0]), "r"(b[1]));
}

// ---------------- tf32 GEMM v2: C[M,N] = A[M,K] * B[N,K]^T ----------------
// Inputs are k-permuted in 8-blocks: permuted slot p holds original k=(p>>1)+(p&1)*4.
// => tf32 fragment pairs (tg, tg+4) are adjacent -> LDS.64 fragment loads.
// BM=128, BN=256, BK=16, 4-stage cp.async pipeline, 256 threads, warp tile 64x64.
#define GBM 128
#define GBN 256
#define GBK 16
#define GSTG 4
#define STG_WORDS 6144                      // A 128*16 + B 256*16 floats
#define GSMEM_BYTES (GSTG * STG_WORDS * 4)  // 96 KB

__global__ __launch_bounds__(256, 1)
void gemm_tf32_v2(const float* __restrict__ A, const float* __restrict__ B,
                  float* __restrict__ C, int M, int N, int K)
{
    extern __shared__ float smem[];
    const uint32_t smem_b = smem_u32(smem);

    const int tid  = threadIdx.x;
    const int lane = tid & 31;
    const int wid  = tid >> 5;
    const int gq   = lane >> 2;         // 0..7
    const int tg   = lane & 3;          // 0..3
    const int m_w  = (wid >> 2) * 64;   // warp m base (2 rows of warps)
    const int n_w  = (wid & 3) * 64;    // warp n base (4 cols of warps)

    // ---- tile swizzle (grouped m for L2 reuse) ----
    const int nTm = M / GBM, nTn = N / GBN;
    constexpr int GROUP = 8;
    const int npg     = GROUP * nTn;
    const int gidx    = blockIdx.x / npg;
    const int first_m = gidx * GROUP;
    const int gsz     = min(nTm - first_m, GROUP);
    const int inG     = blockIdx.x % npg;
    const int m0 = (first_m + (inG % gsz)) * GBM;
    const int n0 = (inG / gsz) * GBN;

    // ---- cp.async stage fill (16B granules, XOR-swizzled by row&3) ----
    const int gr = tid >> 2;        // base row 0..63
    const int gg = tid & 3;         // granule 0..3
    const int gsw = gg ^ (gr & 3);  // same for row+64k (64%4==0)
    const float* Abase = A + (size_t)(m0 + gr) * K + gg * 4;
    const float* Bbase = B + (size_t)(n0 + gr) * K + gg * 4;

    auto load_stage = [&](int s, int kt) {
        const uint32_t sa = smem_b + s * (STG_WORDS * 4);
        const uint32_t sb = sa + 2048 * 4;
        const float* Ag = Abase + kt * GBK;
        const float* Bg = Bbase + kt * GBK;
        // A: rows gr, gr+64
        cp_async16(sa + (gr * 16 + gsw * 4) * 4,          Ag);
        cp_async16(sa + ((gr + 64) * 16 + gsw * 4) * 4,   Ag + (size_t)64 * K);
        // B: rows gr, gr+64, gr+128, gr+192
        #pragma unroll
        for (int j = 0; j < 4; j++)
            cp_async16(sb + ((gr + j * 64) * 16 + gsw * 4) * 4, Bg + (size_t)(j * 64) * K);
        asm volatile("cp.async.commit_group;" ::: "memory");
    };

    // prologue: 3 stages in flight
    #pragma unroll
    for (int s = 0; s < GSTG - 1; s++) load_stage(s, s);

    float acc[4][8][4];
    #pragma unroll
    for (int i = 0; i < 4; i++)
        #pragma unroll
        for (int j = 0; j < 8; j++)
            #pragma unroll
            for (int r = 0; r < 4; r++) acc[i][j][r] = 0.f;

    const int nk = K / GBK;
    for (int kt = 0; kt < nk; ++kt) {
        const int s = kt & (GSTG - 1);
        asm volatile("cp.async.wait_group 2;" ::: "memory");
        __syncthreads();

        if (kt + GSTG - 1 < nk) load_stage((kt + GSTG - 1) & (GSTG - 1), kt + GSTG - 1);
        else asm volatile("cp.async.commit_group;" ::: "memory");

        const float* sa = smem + s * STG_WORDS;
        const float* sb = sa + 2048;

        #pragma unroll
        for (int k8 = 0; k8 < 2; ++k8) {
            // permuted word within row for this thread's k-pair
            const int w   = k8 * 8 + tg * 2;
            const int g   = w >> 2;
            const int wib = w & 3;

            uint32_t af[4][4];
            #pragma unroll
            for (int mt = 0; mt < 4; mt++) {
                const int r0 = m_w + mt * 16 + gq;
                const int r1 = r0 + 8;
                const uint2 v0 = *(const uint2*)(sa + r0 * 16 + ((g ^ (r0 & 3)) << 2) + wib);
                const uint2 v1 = *(const uint2*)(sa + r1 * 16 + ((g ^ (r1 & 3)) << 2) + wib);
                af[mt][0] = v0.x; af[mt][2] = v0.y;   // (k=tg, k=tg+4) row gq
                af[mt][1] = v1.x; af[mt][3] = v1.y;   // row gq+8
            }
            uint32_t bf[8][2];
            #pragma unroll
            for (int nt = 0; nt < 8; nt++) {
                const int rn = n_w + nt * 8 + gq;
                const uint2 v = *(const uint2*)(sb + rn * 16 + ((g ^ (rn & 3)) << 2) + wib);
                bf[nt][0] = v.x; bf[nt][1] = v.y;
            }
            #pragma unroll
            for (int mt = 0; mt < 4; mt++)
                #pragma unroll
                for (int nt = 0; nt < 8; nt++)
                    mma_m16n8k8(acc[mt][nt], af[mt], bf[nt]);
        }
    }

    // epilogue
    #pragma unroll
    for (int mt = 0; mt < 4; mt++) {
        const int r0 = m0 + m_w + mt * 16 + gq;
        #pragma unroll
        for (int nt = 0; nt < 8; nt++) {
            const int c0 = n0 + n_w + nt * 8 + tg * 2;
            *(float2*)&C[(size_t)r0 * N + c0]       = make_float2(acc[mt][nt][0], acc[mt][nt][1]);
            *(float2*)&C[(size_t)(r0 + 8) * N + c0] = make_float2(acc[mt][nt][2], acc[mt][nt][3]);
        }
    }
}

// ---------------- tf32 round + k-permute (8-block [0,4,1,5,2,6,3,7]) ----------------
// out[8i + p] where slot p holds original k=(p>>1)+(p&1)*4
__global__ __launch_bounds__(256)
void round_perm_kernel(const float* __restrict__ in, float* __restrict__ out, int n8)
{
    const int i = blockIdx.x * blockDim.x + threadIdx.x;
    if (i >= n8) return;
    const float4 r0 = ((const float4*)in)[2 * i];       // k 0..3
    const float4 r1 = ((const float4*)in)[2 * i + 1];   // k 4..7
    float4 o0, o1;
    o0.x = rtf32(r0.x); o0.y = rtf32(r1.x); o0.z = rtf32(r0.y); o0.w = rtf32(r1.y);
    o1.x = rtf32(r0.z); o1.y = rtf32(r1.z); o1.z = rtf32(r0.w); o1.w = rtf32(r1.w);
    ((float4*)out)[2 * i]     = o0;
    ((float4*)out)[2 * i + 1] = o1;
}

// ---------------- scan + sigmoid gate (reads natural xz, writes permuted+rounded y) ----------------
__global__ __launch_bounds__(256)
void scan_gate_kernel(const float* __restrict__ A_log,
                      const float* __restrict__ xz,
                      float* __restrict__ y)
{
    using namespace cfg;
    const int idx   = blockIdx.x * blockDim.x + threadIdx.x;
    const int inner = idx % INNER;
    const int bt    = idx / INNER;
    const int t     = bt % CHUNK;
    const int b     = bt / CHUNK;

    const float Ah = expf(-fabsf(A_log[inner >> 6]));
    float hstate = 0.f;

    // permuted write position for GEMM2's k dimension
    const int k7    = inner & 7;
    const int pinner = (inner & ~7) + ((k7 & 3) * 2) + (k7 >> 2);

    size_t xrow = ((size_t)b * Ss + t) * (size_t)N1 + inner;
    size_t yrow = ((size_t)b * Ss + t) * (size_t)INNER + pinner;
    const size_t xstep = (size_t)CHUNK * N1;
    const size_t ystep = (size_t)CHUNK * INNER;

    #pragma unroll
    for (int c = 0; c < NCH; c++) {
        const float xv = xz[xrow];
        const float zv = xz[xrow + INNER];
        hstate = hstate * Ah + 0.1f * xv;
        const float sig = 1.f / (1.f + expf(-zv));
        y[yrow] = rtf32(hstate * sig);
        xrow += xstep;
        yrow += ystep;
    }
}

// ---------------- launch ----------------
extern "C" void kernel_launch(void* const* d_in, const int* in_sizes, int n_in,
                              void* d_out, int out_size)
{
    using namespace cfg;
    const float* hs    = (const float*)d_in[0];
    const float* W_in  = (const float*)d_in[1];
    const float* W_out = (const float*)d_in[2];
    const float* A_log = (const float*)d_in[3];
    float* out = (float*)d_out;

    float *xz, *y, *a1, *w1, *w2;
    cudaGetSymbolAddress((void**)&xz, g_xz);
    cudaGetSymbolAddress((void**)&y,  g_y);
    cudaGetSymbolAddress((void**)&a1, g_a1);
    cudaGetSymbolAddress((void**)&w1, g_w1);
    cudaGetSymbolAddress((void**)&w2, g_w2);

    cudaFuncSetAttribute(gemm_tf32_v2, cudaFuncAttributeMaxDynamicSharedMemorySize, GSMEM_BYTES);

    // round to tf32 + k-permute all GEMM operands
    {
        int n8;
        n8 = (M1 * K1) / 8; round_perm_kernel<<<(n8 + 255) / 256, 256>>>(hs,    a1, n8);
        n8 = (N1 * K1) / 8; round_perm_kernel<<<(n8 + 255) / 256, 256>>>(W_in,  w1, n8);
        n8 = (N2 * K2) / 8; round_perm_kernel<<<(n8 + 255) / 256, 256>>>(W_out, w2, n8);
    }

    // GEMM1: xz = hs @ W_in^T   (M=8192, N=14336, K=3584)
    gemm_tf32_v2<<<(M1 / GBM) * (N1 / GBN), 256, GSMEM_BYTES>>>(a1, w1, xz, M1, N1, K1);

    // scan + gate (writes permuted y)
    const int total = Bb * CHUNK * INNER;
    scan_gate_kernel<<<total / 256, 256>>>(A_log, xz, y);

    // GEMM2: out = y @ W_out^T  (M=8192, N=3584, K=7168)
    gemm_tf32_v2<<<(M1 / GBM) * (N2 / GBN), 256, GSMEM_BYTES>>>(y, w2, out, M1, N2, K2);
}